// round 6
// baseline (speedup 1.0000x reference)
#include <cuda_runtime.h>
#include <cstdint>

// ---------------------------------------------------------------------------
// 4D ConvTranspose stride2 K=3^4 as 16 parity-class GEMMs on int8 tensor cores
// (ldmatrix + mma.sync m16n8k32 s8, s32 accum), 3-term fixed-point split:
//   x ~= sx*(xh + xl/128), w ~= sw*(wh + wl/128)
//   out += sx*sw*( Dhi + Dmid/128 ),  Dhi=sum xh*wh, Dmid=sum(xh*wl + xl*wh)
// Double-buffered cp.async staging across taps.
// ---------------------------------------------------------------------------

#define XM 20736            // 12^4 input spatial points
#define OSB 25000000LL
#define OSC 390625
#define OS1 15625
#define OS2 625
#define OS3 25

// quantized operands
__device__ __align__(16) int8_t g_wh8[81*64*64];   // [kidx][co][ci]
__device__ __align__(16) int8_t g_wl8[81*64*64];
__device__ float  g_sw[81*64];                     // [kidx][co]
__device__ __align__(16) int8_t g_xh8[4L*XM*64];   // [b][m_lin][ci]
__device__ __align__(16) int8_t g_xl8[4L*XM*64];
__device__ float  g_sx[4*XM];                      // [b][m_lin]

// dynamic SMEM layout. A rows pitch 80B (5r+q mod 8 conflict-free), B same.
#define SM_AH   0            // 2 bufs x 256 rows x 80B = 40960
#define SM_AL   40960        // 40960
#define SM_BH   81920        // 2 bufs x 64 rows x 80B = 10240
#define SM_BL   92160        // 10240
#define SM_OFFS 102400       // u16[16*256] = 8192
#define SM_SXA  110592       // 2 x float[256] = 2048
#define SM_SWC  112640       // 2 x float[64]  = 512
#define SM_BIAS 113152       // float[64]
#define SM_KOF  113408       // int[16]
#define SM_DD   113472       // char[16][4]
#define SM_TOTAL 113536

// ---------------- prep kernels ----------------
// W rows: per (kidx, co) over 64 ci (strided gather from torch layout)
__global__ void wq_prep(const float* __restrict__ w) {
    int rid = blockIdx.x * 128 + threadIdx.x;
    if (rid >= 5184) return;                 // 81*64
    int k = rid >> 6, co = rid & 63;
    float mx = 0.f;
    for (int ci = 0; ci < 64; ci++)
        mx = fmaxf(mx, fabsf(w[ci * 5184 + co * 81 + k]));
    float sc = mx > 0.f ? mx * (1.f / 127.f) : 1.f;
    float inv = 1.f / sc;
    for (int ci = 0; ci < 64; ci++) {
        float v = w[ci * 5184 + co * 81 + k];
        int hq = __float2int_rn(v * inv);
        float r = v - sc * (float)hq;
        int lq = __float2int_rn(r * inv * 128.f);
        g_wh8[(k * 64 + co) * 64 + ci] = (int8_t)hq;
        g_wl8[(k * 64 + co) * 64 + ci] = (int8_t)lq;
    }
    g_sw[k * 64 + co] = sc;
}

// X rows: transpose [b][ci][m] -> per (b,m) row of 64 ci, quantize
__global__ void xq_prep(const float* __restrict__ x) {
    __shared__ float s[64][33];
    int b = blockIdx.y, m0 = blockIdx.x * 32, tid = threadIdx.x;
    for (int i = tid; i < 2048; i += 256) {
        int ci = i >> 5, mm = i & 31;
        s[ci][mm] = x[((size_t)(b * 64 + ci)) * XM + m0 + mm];
    }
    __syncthreads();
    int rid = tid >> 3, sub = tid & 7;     // 32 rows x 8 threads
    float v[8], mx = 0.f;
    #pragma unroll
    for (int j = 0; j < 8; j++) {
        v[j] = s[sub * 8 + j][rid];
        mx = fmaxf(mx, fabsf(v[j]));
    }
    #pragma unroll
    for (int o = 1; o < 8; o <<= 1)
        mx = fmaxf(mx, __shfl_xor_sync(0xFFFFFFFFu, mx, o));
    float sc = mx > 0.f ? mx * (1.f / 127.f) : 1.f;
    float inv = 1.f / sc;
    uint32_t hp[2] = {0, 0}, lp[2] = {0, 0};
    #pragma unroll
    for (int j = 0; j < 8; j++) {
        int hq = __float2int_rn(v[j] * inv);
        float r = v[j] - sc * (float)hq;
        int lq = __float2int_rn(r * inv * 128.f);
        hp[j >> 2] |= (uint32_t)(hq & 0xff) << ((j & 3) * 8);
        lp[j >> 2] |= (uint32_t)(lq & 0xff) << ((j & 3) * 8);
    }
    size_t ro = ((size_t)b * XM + m0 + rid) * 64 + sub * 8;
    *(uint2*)(g_xh8 + ro) = make_uint2(hp[0], hp[1]);
    *(uint2*)(g_xl8 + ro) = make_uint2(lp[0], lp[1]);
    if (sub == 0) g_sx[b * XM + m0 + rid] = sc;
}

// ---------------- ptx helpers ----------------
__device__ __forceinline__ uint32_t smem_u32(const void* p) {
    uint32_t a;
    asm("{ .reg .u64 t; cvta.to.shared.u64 t, %1; cvt.u32.u64 %0, t; }" : "=r"(a) : "l"(p));
    return a;
}
__device__ __forceinline__ void ldsm4(uint32_t r[4], uint32_t addr) {
    asm volatile("ldmatrix.sync.aligned.m8n8.x4.shared.b16 {%0,%1,%2,%3}, [%4];"
                 : "=r"(r[0]), "=r"(r[1]), "=r"(r[2]), "=r"(r[3]) : "r"(addr));
}
__device__ __forceinline__ void mma_s8(int c[4], const uint32_t a[4],
                                       uint32_t b0, uint32_t b1) {
    asm volatile("mma.sync.aligned.m16n8k32.row.col.s32.s8.s8.s32 "
                 "{%0,%1,%2,%3}, {%4,%5,%6,%7}, {%8,%9}, {%0,%1,%2,%3};"
                 : "+r"(c[0]), "+r"(c[1]), "+r"(c[2]), "+r"(c[3])
                 : "r"(a[0]), "r"(a[1]), "r"(a[2]), "r"(a[3]), "r"(b0), "r"(b1));
}
__device__ __forceinline__ void cpa16(uint32_t dst, const void* src, bool pred) {
    int sz = pred ? 16 : 0;
    asm volatile("cp.async.cg.shared.global [%0], [%1], 16, %2;"
                 :: "r"(dst), "l"(src), "r"(sz) : "memory");
}

// ---------------- main kernel ----------------
__global__ __launch_bounds__(256) void ct4d_mma(
    const float* __restrict__ bias, float* __restrict__ out)
{
    extern __shared__ char smem[];
    const int tid = threadIdx.x, lane = tid & 31, wrp = tid >> 5;
    const int c = blockIdx.z, b = blockIdx.y, tile = blockIdx.x;
    const int p1 = (c >> 3) & 1, p2 = (c >> 2) & 1, p3 = (c >> 1) & 1, p4 = c & 1;
    const int n1 = 13 - p1, n2 = 13 - p2, n3 = 13 - p3, n4 = 13 - p4;
    const int Ntot = n1 * n2 * n3 * n4;
    if (tile * 256 >= Ntot) return;
    const int lgT = 4 - p1 - p2 - p3 - p4;
    const int T = 1 << lgT;

    const uint32_t sb = smem_u32(smem);
    int*          kof  = (int*)(smem + SM_KOF);
    signed char (*dd)[4] = (signed char(*)[4])(smem + SM_DD);
    uint16_t*     offs = (uint16_t*)(smem + SM_OFFS);
    float*        sxa  = (float*)(smem + SM_SXA);
    float*        swc  = (float*)(smem + SM_SWC);
    float*        bs   = (float*)(smem + SM_BIAS);

    if (tid < T) {
        int rem = tid, pp[4] = {p1, p2, p3, p4}, d[4], k[4];
        #pragma unroll
        for (int i = 0; i < 4; i++) {
            if (!pp[i]) { d[i] = rem & 1; rem >>= 1; k[i] = 2 * d[i]; }
            else        { d[i] = 0;                  k[i] = 1; }
        }
        kof[tid] = ((k[0] * 3 + k[1]) * 3 + k[2]) * 3 + k[3];
        dd[tid][0] = d[0]; dd[tid][1] = d[1]; dd[tid][2] = d[2]; dd[tid][3] = d[3];
    }
    if (tid < 64) bs[tid] = bias[tid];
    __syncthreads();

    // gather offsets per (tap, sp row); 0xFFFF = OOB/pad
    {
        int g = tile * 256 + tid;
        int valid = g < Ntot, m1 = 0, m2 = 0, m3 = 0, m4 = 0;
        if (valid) { m4 = g % n4; int q = g / n4; m3 = q % n3; q /= n3; m2 = q % n2; m1 = q / n2; }
        for (int t = 0; t < T; t++) {
            int off = 0xFFFF;
            if (valid) {
                int a1 = m1 - dd[t][0], a2 = m2 - dd[t][1], a3 = m3 - dd[t][2], a4 = m4 - dd[t][3];
                if (((unsigned)a1 < 12u) & ((unsigned)a2 < 12u) & ((unsigned)a3 < 12u) & ((unsigned)a4 < 12u))
                    off = ((a1 * 12 + a2) * 12 + a3) * 12 + a4;
            }
            offs[t * 256 + tid] = (uint16_t)off;
        }
    }

    auto stage = [&](int t, int bf) {
        const int kb = kof[t] * 64;
        {   // B: 64 rows x 64B
            int r = tid >> 2, q = tid & 3;
            uint32_t so = bf * 5120 + r * 80 + q * 16;
            cpa16(sb + SM_BH + so, g_wh8 + (kb + r) * 64 + q * 16, true);
            cpa16(sb + SM_BL + so, g_wl8 + (kb + r) * 64 + q * 16, true);
        }
        if (tid < 64) swc[bf * 64 + tid] = g_sw[kb + tid];
        {   // A: 256 rows x 64B, row per thread
            uint32_t off = offs[t * 256 + tid];
            bool ok = off != 0xFFFFu;
            sxa[bf * 256 + tid] = ok ? g_sx[b * XM + off] : 0.f;
            size_t go = ((size_t)b * XM + (ok ? off : 0)) * 64;
            uint32_t ab = bf * 20480 + tid * 80;
            #pragma unroll
            for (int q = 0; q < 4; q++) {
                cpa16(sb + SM_AH + ab + q * 16, g_xh8 + go + q * 16, ok);
                cpa16(sb + SM_AL + ab + q * 16, g_xl8 + go + q * 16, ok);
            }
        }
        asm volatile("cp.async.commit_group;" ::: "memory");
    };

    float acc[2][8][4];
    #pragma unroll
    for (int i = 0; i < 2; i++)
        #pragma unroll
        for (int j = 0; j < 8; j++)
            #pragma unroll
            for (int q = 0; q < 4; q++) acc[i][j][q] = 0.f;

    stage(0, 0);   // uses only this thread's offs rows + kof (barriered)

    const int arow_s = lane & 15;
    const int aseg   = (lane >> 4) * 16;
    const int brow_s = ((lane >> 4) & 1) * 8 + (lane & 7);
    const int bseg   = ((lane >> 3) & 1) * 16;

    for (int t = 0; t < T; t++) {
        const int bf = t & 1;
        if (t + 1 < T) {
            stage(t + 1, bf ^ 1);
            asm volatile("cp.async.wait_group 1;" ::: "memory");
        } else {
            asm volatile("cp.async.wait_group 0;" ::: "memory");
        }
        __syncthreads();

        // ---- compute on buffer bf ----
        uint32_t Ah[2][2][4], Al[2][2][4];
        const uint32_t abase  = sb + SM_AH + bf * 20480;
        const uint32_t albase = sb + SM_AL + bf * 20480;
        #pragma unroll
        for (int i = 0; i < 2; i++)
            #pragma unroll
            for (int k = 0; k < 2; k++) {
                uint32_t ao = (wrp * 32 + i * 16 + arow_s) * 80 + k * 32 + aseg;
                ldsm4(Ah[i][k], abase + ao);
                ldsm4(Al[i][k], albase + ao);
            }
        float sxr[2][2];
        #pragma unroll
        for (int i = 0; i < 2; i++) {
            sxr[i][0] = sxa[bf * 256 + wrp * 32 + i * 16 + (lane >> 2)];
            sxr[i][1] = sxa[bf * 256 + wrp * 32 + i * 16 + (lane >> 2) + 8];
        }
        const uint32_t bbase  = sb + SM_BH + bf * 5120;
        const uint32_t blbase = sb + SM_BL + bf * 5120;
        #pragma unroll
        for (int jj = 0; jj < 4; jj++) {
            uint32_t Bh[2][4], Bl[2][4];
            #pragma unroll
            for (int k = 0; k < 2; k++) {
                uint32_t bo = (jj * 16 + brow_s) * 80 + k * 32 + bseg;
                ldsm4(Bh[k], bbase + bo);
                ldsm4(Bl[k], blbase + bo);
            }
            #pragma unroll
            for (int jo = 0; jo < 2; jo++) {
                const int j = jj * 2 + jo;
                float u0 = swc[bf * 64 + j * 8 + (lane & 3) * 2]     * 0.0078125f;
                float u1 = swc[bf * 64 + j * 8 + (lane & 3) * 2 + 1] * 0.0078125f;
                #pragma unroll
                for (int i = 0; i < 2; i++) {
                    int dhi[4] = {0, 0, 0, 0}, dm[4] = {0, 0, 0, 0};
                    #pragma unroll
                    for (int k = 0; k < 2; k++) {
                        mma_s8(dhi, Ah[i][k], Bh[k][2 * jo], Bh[k][2 * jo + 1]);
                        mma_s8(dm,  Ah[i][k], Bl[k][2 * jo], Bl[k][2 * jo + 1]);
                        mma_s8(dm,  Al[i][k], Bh[k][2 * jo], Bh[k][2 * jo + 1]);
                    }
                    acc[i][j][0] += (sxr[i][0] * u0) * (float)((dhi[0] << 7) + dm[0]);
                    acc[i][j][1] += (sxr[i][0] * u1) * (float)((dhi[1] << 7) + dm[1]);
                    acc[i][j][2] += (sxr[i][1] * u0) * (float)((dhi[2] << 7) + dm[2]);
                    acc[i][j][3] += (sxr[i][1] * u1) * (float)((dhi[3] << 7) + dm[3]);
                }
            }
        }
        if (t + 1 < T) __syncthreads();  // before next iter re-stages buffer bf
    }

    // epilogue: strided scatter into the class sub-grid
    float* ob = out + (size_t)b * OSB;
    const int gbase = tile * 256 + wrp * 32 + (lane >> 2);
    #pragma unroll
    for (int i = 0; i < 2; i++) {
        #pragma unroll
        for (int h = 0; h < 2; h++) {
            int g = gbase + i * 16 + h * 8;
            if (g >= Ntot) continue;
            int m4 = g % n4; int q = g / n4;
            int m3 = q % n3; q /= n3;
            int m2 = q % n2; int m1 = q / n2;
            long o = (long)(2 * m1 + p1) * OS1 + (2 * m2 + p2) * OS2 +
                     (2 * m3 + p3) * OS3 + (2 * m4 + p4);
            float* op = ob + o;
            #pragma unroll
            for (int j = 0; j < 8; j++) {
                int co = j * 8 + (lane & 3) * 2;
                op[(size_t)co * OSC]       = acc[i][j][2 * h]     + bs[co];
                op[(size_t)(co + 1) * OSC] = acc[i][j][2 * h + 1] + bs[co + 1];
            }
        }
    }
}

extern "C" void kernel_launch(void* const* d_in, const int* in_sizes, int n_in,
                              void* d_out, int out_size) {
    const float* x    = (const float*)d_in[0];
    const float* w    = (const float*)d_in[1];
    const float* bias = (const float*)d_in[2];
    float* out = (float*)d_out;

    cudaFuncSetAttribute(ct4d_mma, cudaFuncAttributeMaxDynamicSharedMemorySize, SM_TOTAL);

    wq_prep<<<41, 128>>>(w);
    xq_prep<<<dim3(648, 4), 256>>>(x);
    // 112 = ceil(13^4 / 256); smaller classes early-exit surplus tiles.
    ct4d_mma<<<dim3(112, 4, 16), 256, SM_TOTAL>>>(bias, out);
}

// round 8
// speedup vs baseline: 3.0954x; 3.0954x over previous
#include <cuda_runtime.h>
#include <cuda_fp16.h>
#include <cstdint>

// ---------------------------------------------------------------------------
// 4D ConvTranspose stride2 K=3^4 as 16 parity-class GEMMs on tensor cores
// (ldmatrix + mma.sync m16n8k16 f16, fp32 accum).
//   D[sp=256, co=64] += X[sp, k]·W[co, k],  k = (tap t, ci),  K = 64*T
// Asymmetric precision: W split into fp16 hi+lo (exact, prescaled x64),
// X single fp16 (error ~2^-11, random-walk over K -> ~2e-4 rel).
// Ping-pong double-buffered cp.async staging across taps.
// R8 fix: B staging now covers all 64 co rows at 128 threads (R7 bug: only 32).
// ---------------------------------------------------------------------------

#define XM 20736            // 12^4 input spatial points
#define OSB 25000000LL
#define OSC 390625
#define OS1 15625
#define OS2 625
#define OS3 25

// prepped operands
__device__ __align__(16) __half g_w16h[81*64*64];  // [kidx][co][ci], x64 scaled
__device__ __align__(16) __half g_w16l[81*64*64];
__device__ __align__(16) __half g_x16[4L*XM*64];   // [b][m_lin][ci]

// dynamic SMEM: ping-pong buffers. Rows 128B, XOR-swizzled.
#define SM_A    0            // 2 bufs x 256 rows x 128B = 65536
#define SM_BH   65536        // 2 bufs x 64 rows x 128B = 16384
#define SM_BL   81920        // 16384
#define SM_OFFS 98304        // u16[16*256] = 8192
#define SM_BIAS 106496       // float[64]
#define SM_KOF  106752       // int[16]
#define SM_DD   106816       // char[16][4]
#define SM_TOTAL 106880

#define SWZ(o) ((o) ^ (((o) >> 3) & 0x70))

// ---------------- prep kernels ----------------
__global__ void wq_prep(const float* __restrict__ w) {
    int idx = blockIdx.x * 256 + threadIdx.x;
    if (idx >= 331776) return;                 // 64*64*81
    int ci = idx / 5184;
    int r  = idx - ci * 5184;
    int co = r / 81;
    int k  = r - co * 81;
    float v = w[idx] * 64.f;                   // prescale keeps lo limb normal
    __half h = __float2half(v);
    __half l = __float2half(v - __half2float(h));
    int o = (k * 64 + co) * 64 + ci;
    g_w16h[o] = h; g_w16l[o] = l;
}

__global__ void xq_prep(const float* __restrict__ x) {
    __shared__ float s[64][33];
    int b = blockIdx.y, m0 = blockIdx.x * 32, tid = threadIdx.x;
    for (int i = tid; i < 2048; i += 256) {
        int ci = i >> 5, mm = i & 31;
        s[ci][mm] = x[((size_t)(b * 64 + ci)) * XM + m0 + mm];
    }
    __syncthreads();
    int m = tid >> 3, q = tid & 7;
    union { __half a[8]; uint4 v; } hv;
    #pragma unroll
    for (int j = 0; j < 8; j++)
        hv.a[j] = __float2half(s[q * 8 + j][m]);
    *(uint4*)(g_x16 + ((size_t)b * XM + m0 + m) * 64 + q * 8) = hv.v;
}

// ---------------- ptx helpers ----------------
__device__ __forceinline__ uint32_t smem_u32(const void* p) {
    uint32_t a;
    asm("{ .reg .u64 t; cvta.to.shared.u64 t, %1; cvt.u32.u64 %0, t; }" : "=r"(a) : "l"(p));
    return a;
}
__device__ __forceinline__ void ldsm4(uint32_t r[4], uint32_t addr) {
    asm volatile("ldmatrix.sync.aligned.m8n8.x4.shared.b16 {%0,%1,%2,%3}, [%4];"
                 : "=r"(r[0]), "=r"(r[1]), "=r"(r[2]), "=r"(r[3]) : "r"(addr));
}
__device__ __forceinline__ void mma_f16(float c[4], const uint32_t a[4],
                                        uint32_t b0, uint32_t b1) {
    asm volatile("mma.sync.aligned.m16n8k16.row.col.f32.f16.f16.f32 "
                 "{%0,%1,%2,%3}, {%4,%5,%6,%7}, {%8,%9}, {%0,%1,%2,%3};"
                 : "+f"(c[0]), "+f"(c[1]), "+f"(c[2]), "+f"(c[3])
                 : "r"(a[0]), "r"(a[1]), "r"(a[2]), "r"(a[3]), "r"(b0), "r"(b1));
}
__device__ __forceinline__ void cpa16(uint32_t dst, const void* src, bool pred) {
    int sz = pred ? 16 : 0;
    asm volatile("cp.async.cg.shared.global [%0], [%1], 16, %2;"
                 :: "r"(dst), "l"(src), "r"(sz) : "memory");
}

// ---------------- main kernel ----------------
__global__ __launch_bounds__(128) void ct4d_mma(
    const float* __restrict__ bias, float* __restrict__ out)
{
    extern __shared__ char smem[];
    const int tid = threadIdx.x, lane = tid & 31, wrp = tid >> 5;
    const int c = blockIdx.z, b = blockIdx.y, tile = blockIdx.x;
    const int p1 = (c >> 3) & 1, p2 = (c >> 2) & 1, p3 = (c >> 1) & 1, p4 = c & 1;
    const int n1 = 13 - p1, n2 = 13 - p2, n3 = 13 - p3, n4 = 13 - p4;
    const int Ntot = n1 * n2 * n3 * n4;
    if (tile * 256 >= Ntot) return;
    const int lgT = 4 - p1 - p2 - p3 - p4;
    const int T = 1 << lgT;

    const uint32_t sb = smem_u32(smem);
    int*          kof  = (int*)(smem + SM_KOF);
    signed char (*dd)[4] = (signed char(*)[4])(smem + SM_DD);
    uint16_t*     offs = (uint16_t*)(smem + SM_OFFS);
    float*        bs   = (float*)(smem + SM_BIAS);

    if (tid < T) {
        int rem = tid, pp[4] = {p1, p2, p3, p4}, d[4], k[4];
        #pragma unroll
        for (int i = 0; i < 4; i++) {
            if (!pp[i]) { d[i] = rem & 1; rem >>= 1; k[i] = 2 * d[i]; }
            else        { d[i] = 0;                  k[i] = 1; }
        }
        kof[tid] = ((k[0] * 3 + k[1]) * 3 + k[2]) * 3 + k[3];
        dd[tid][0] = d[0]; dd[tid][1] = d[1]; dd[tid][2] = d[2]; dd[tid][3] = d[3];
    }
    if (tid < 64) bs[tid] = bias[tid];
    __syncthreads();

    // gather offsets per (tap, sp row); 0xFFFF = OOB/pad
    for (int s = tid; s < 256; s += 128) {
        int g = tile * 256 + s;
        int valid = g < Ntot, m1 = 0, m2 = 0, m3 = 0, m4 = 0;
        if (valid) { m4 = g % n4; int q = g / n4; m3 = q % n3; q /= n3; m2 = q % n2; m1 = q / n2; }
        for (int t = 0; t < T; t++) {
            int off = 0xFFFF;
            if (valid) {
                int a1 = m1 - dd[t][0], a2 = m2 - dd[t][1], a3 = m3 - dd[t][2], a4 = m4 - dd[t][3];
                if (((unsigned)a1 < 12u) & ((unsigned)a2 < 12u) & ((unsigned)a3 < 12u) & ((unsigned)a4 < 12u))
                    off = ((a1 * 12 + a2) * 12 + a3) * 12 + a4;
            }
            offs[t * 256 + s] = (uint16_t)off;
        }
    }
    __syncthreads();   // offs visible to all threads before staging

    const __half* xb = g_x16 + (size_t)b * XM * 64;

    auto stage = [&](int t, int bf) {
        // B: 64 co rows x 128B, hi + lo limbs.
        // 128 threads: 4 threads/row x 2 segs -> 32 rows/pass, 2 passes.
        {
            const int kb = kof[t] * 64;
            int r0 = tid >> 2, q = tid & 3;
            #pragma unroll
            for (int rb = 0; rb < 2; rb++) {
                int r = r0 + rb * 32;
                #pragma unroll
                for (int s = 0; s < 2; s++) {
                    int seg = q * 2 + s;
                    uint32_t so = bf * 8192 + SWZ(r * 128 + seg * 16);
                    cpa16(sb + SM_BH + so, g_w16h + (kb + r) * 64 + seg * 8, true);
                    cpa16(sb + SM_BL + so, g_w16l + (kb + r) * 64 + seg * 8, true);
                }
            }
        }
        // A: 256 sp rows x 128B, single limb (8 threads/row, 16 rows/pass)
        {
            const uint16_t* ot = offs + t * 256;
            int q8 = tid & 7, rsub = tid >> 3;
            #pragma unroll
            for (int rb = 0; rb < 256; rb += 16) {
                int r = rb + rsub;
                uint32_t off = ot[r];
                bool ok = off != 0xFFFFu;
                uint32_t so = bf * 32768 + SWZ(r * 128 + q8 * 16);
                cpa16(sb + SM_A + so, xb + (size_t)(ok ? off : 0) * 64 + q8 * 8, ok);
            }
        }
        asm volatile("cp.async.commit_group;" ::: "memory");
    };

    float acc[4][8][4];
    #pragma unroll
    for (int i = 0; i < 4; i++)
        #pragma unroll
        for (int j = 0; j < 8; j++)
            #pragma unroll
            for (int q = 0; q < 4; q++) acc[i][j][q] = 0.f;

    stage(0, 0);

    const int arow_s = lane & 15;
    const int aseg   = ((lane >> 4) & 1) * 16;
    const int brow_s = ((lane >> 4) & 1) * 8 + (lane & 7);
    const int bseg   = ((lane >> 3) & 1) * 16;

    for (int t = 0; t < T; t++) {
        const int bf = t & 1;
        if (t + 1 < T) {
            stage(t + 1, bf ^ 1);
            asm volatile("cp.async.wait_group 1;" ::: "memory");
        } else {
            asm volatile("cp.async.wait_group 0;" ::: "memory");
        }
        __syncthreads();

        const uint32_t abase  = sb + SM_A  + bf * 32768;
        const uint32_t bhbase = sb + SM_BH + bf * 8192;
        const uint32_t blbase = sb + SM_BL + bf * 8192;

        #pragma unroll
        for (int kk = 0; kk < 4; kk++) {
            uint32_t Af[4][4];
            const uint32_t acol = kk * 32 + aseg;
            #pragma unroll
            for (int i = 0; i < 4; i++)
                ldsm4(Af[i], abase + SWZ((wrp * 64 + i * 16 + arow_s) * 128 + acol));
            #pragma unroll
            for (int jp = 0; jp < 4; jp++) {
                uint32_t Bh[4], Bl[4];
                uint32_t bo = SWZ((jp * 16 + brow_s) * 128 + kk * 32 + bseg);
                ldsm4(Bh, bhbase + bo);
                ldsm4(Bl, blbase + bo);
                #pragma unroll
                for (int i = 0; i < 4; i++) {
                    mma_f16(acc[i][2 * jp],     Af[i], Bh[0], Bh[1]);
                    mma_f16(acc[i][2 * jp],     Af[i], Bl[0], Bl[1]);
                    mma_f16(acc[i][2 * jp + 1], Af[i], Bh[2], Bh[3]);
                    mma_f16(acc[i][2 * jp + 1], Af[i], Bl[2], Bl[3]);
                }
            }
        }
        if (t + 1 < T) __syncthreads();  // all warps done with bf before restage
    }

    // epilogue: undo x64 weight prescale, bias, strided scatter
    float* ob = out + (size_t)b * OSB;
    const int gbase = tile * 256 + wrp * 64 + (lane >> 2);
    #pragma unroll
    for (int i = 0; i < 4; i++) {
        #pragma unroll
        for (int h = 0; h < 2; h++) {
            int g = gbase + i * 16 + h * 8;
            if (g >= Ntot) continue;
            int m4 = g % n4; int q = g / n4;
            int m3 = q % n3; q /= n3;
            int m2 = q % n2; int m1 = q / n2;
            long o = (long)(2 * m1 + p1) * OS1 + (2 * m2 + p2) * OS2 +
                     (2 * m3 + p3) * OS3 + (2 * m4 + p4);
            float* op = ob + o;
            #pragma unroll
            for (int j = 0; j < 8; j++) {
                int co = j * 8 + (lane & 3) * 2;
                op[(size_t)co * OSC]       = acc[i][j][2 * h]     * 0.015625f + bs[co];
                op[(size_t)(co + 1) * OSC] = acc[i][j][2 * h + 1] * 0.015625f + bs[co + 1];
            }
        }
    }
}

extern "C" void kernel_launch(void* const* d_in, const int* in_sizes, int n_in,
                              void* d_out, int out_size) {
    const float* x    = (const float*)d_in[0];
    const float* w    = (const float*)d_in[1];
    const float* bias = (const float*)d_in[2];
    float* out = (float*)d_out;

    cudaFuncSetAttribute(ct4d_mma, cudaFuncAttributeMaxDynamicSharedMemorySize, SM_TOTAL);

    wq_prep<<<1296, 256>>>(w);
    xq_prep<<<dim3(648, 4), 256>>>(x);
    // 112 = ceil(13^4 / 256); smaller classes early-exit surplus tiles.
    ct4d_mma<<<dim3(112, 4, 16), 128, SM_TOTAL>>>(bias, out);
}

// round 9
// speedup vs baseline: 3.4023x; 1.0992x over previous
#include <cuda_runtime.h>
#include <cuda_fp16.h>
#include <cstdint>

// ---------------------------------------------------------------------------
// 4D ConvTranspose stride2 K=3^4 as 16 parity-class GEMMs on tensor cores
// (ldmatrix + mma.sync m16n8k16 f16, fp32 accum).
//   D[sp=256, co=64] += X[sp, k]·W[co, k],  k = (tap t, ci),  K = 64*T
// R9: single-term fp16 (both X and W single fp16). Independent rounding
// random-walks -> rel_err ~3e-4 (< 1e-3). Halves MMA count vs R8 on the
// half-rate fp32-acc HMMA path (the measured binding resource).
// Ping-pong double-buffered cp.async staging across taps.
// ---------------------------------------------------------------------------

#define XM 20736            // 12^4 input spatial points
#define OSB 25000000LL
#define OSC 390625
#define OS1 15625
#define OS2 625
#define OS3 25

// prepped operands
__device__ __align__(16) __half g_w16[81*64*64];   // [kidx][co][ci]
__device__ __align__(16) __half g_x16[4L*XM*64];   // [b][m_lin][ci]

// dynamic SMEM: ping-pong buffers. Rows 128B, XOR-swizzled.
#define SM_A    0            // 2 bufs x 256 rows x 128B = 65536
#define SM_B    65536        // 2 bufs x 64 rows x 128B = 16384
#define SM_OFFS 81920        // u16[16*256] = 8192
#define SM_BIAS 90112        // float[64]
#define SM_KOF  90368        // int[16]
#define SM_DD   90432        // char[16][4]
#define SM_TOTAL 90496

#define SWZ(o) ((o) ^ (((o) >> 3) & 0x70))

// ---------------- prep kernels ----------------
__global__ void wq_prep(const float* __restrict__ w) {
    int idx = blockIdx.x * 256 + threadIdx.x;
    if (idx >= 331776) return;                 // 64*64*81
    int ci = idx / 5184;
    int r  = idx - ci * 5184;
    int co = r / 81;
    int k  = r - co * 81;
    g_w16[(k * 64 + co) * 64 + ci] = __float2half(w[idx]);
}

__global__ void xq_prep(const float* __restrict__ x) {
    __shared__ float s[64][33];
    int b = blockIdx.y, m0 = blockIdx.x * 32, tid = threadIdx.x;
    for (int i = tid; i < 2048; i += 256) {
        int ci = i >> 5, mm = i & 31;
        s[ci][mm] = x[((size_t)(b * 64 + ci)) * XM + m0 + mm];
    }
    __syncthreads();
    int m = tid >> 3, q = tid & 7;
    union { __half a[8]; uint4 v; } hv;
    #pragma unroll
    for (int j = 0; j < 8; j++)
        hv.a[j] = __float2half(s[q * 8 + j][m]);
    *(uint4*)(g_x16 + ((size_t)b * XM + m0 + m) * 64 + q * 8) = hv.v;
}

// ---------------- ptx helpers ----------------
__device__ __forceinline__ uint32_t smem_u32(const void* p) {
    uint32_t a;
    asm("{ .reg .u64 t; cvta.to.shared.u64 t, %1; cvt.u32.u64 %0, t; }" : "=r"(a) : "l"(p));
    return a;
}
__device__ __forceinline__ void ldsm4(uint32_t r[4], uint32_t addr) {
    asm volatile("ldmatrix.sync.aligned.m8n8.x4.shared.b16 {%0,%1,%2,%3}, [%4];"
                 : "=r"(r[0]), "=r"(r[1]), "=r"(r[2]), "=r"(r[3]) : "r"(addr));
}
__device__ __forceinline__ void mma_f16(float c[4], const uint32_t a[4],
                                        uint32_t b0, uint32_t b1) {
    asm volatile("mma.sync.aligned.m16n8k16.row.col.f32.f16.f16.f32 "
                 "{%0,%1,%2,%3}, {%4,%5,%6,%7}, {%8,%9}, {%0,%1,%2,%3};"
                 : "+f"(c[0]), "+f"(c[1]), "+f"(c[2]), "+f"(c[3])
                 : "r"(a[0]), "r"(a[1]), "r"(a[2]), "r"(a[3]), "r"(b0), "r"(b1));
}
__device__ __forceinline__ void cpa16(uint32_t dst, const void* src, bool pred) {
    int sz = pred ? 16 : 0;
    asm volatile("cp.async.cg.shared.global [%0], [%1], 16, %2;"
                 :: "r"(dst), "l"(src), "r"(sz) : "memory");
}

// ---------------- main kernel ----------------
__global__ __launch_bounds__(128) void ct4d_mma(
    const float* __restrict__ bias, float* __restrict__ out)
{
    extern __shared__ char smem[];
    const int tid = threadIdx.x, lane = tid & 31, wrp = tid >> 5;
    const int c = blockIdx.z, b = blockIdx.y, tile = blockIdx.x;
    const int p1 = (c >> 3) & 1, p2 = (c >> 2) & 1, p3 = (c >> 1) & 1, p4 = c & 1;
    const int n1 = 13 - p1, n2 = 13 - p2, n3 = 13 - p3, n4 = 13 - p4;
    const int Ntot = n1 * n2 * n3 * n4;
    if (tile * 256 >= Ntot) return;
    const int lgT = 4 - p1 - p2 - p3 - p4;
    const int T = 1 << lgT;

    const uint32_t sb = smem_u32(smem);
    int*          kof  = (int*)(smem + SM_KOF);
    signed char (*dd)[4] = (signed char(*)[4])(smem + SM_DD);
    uint16_t*     offs = (uint16_t*)(smem + SM_OFFS);
    float*        bs   = (float*)(smem + SM_BIAS);

    if (tid < T) {
        int rem = tid, pp[4] = {p1, p2, p3, p4}, d[4], k[4];
        #pragma unroll
        for (int i = 0; i < 4; i++) {
            if (!pp[i]) { d[i] = rem & 1; rem >>= 1; k[i] = 2 * d[i]; }
            else        { d[i] = 0;                  k[i] = 1; }
        }
        kof[tid] = ((k[0] * 3 + k[1]) * 3 + k[2]) * 3 + k[3];
        dd[tid][0] = d[0]; dd[tid][1] = d[1]; dd[tid][2] = d[2]; dd[tid][3] = d[3];
    }
    if (tid < 64) bs[tid] = bias[tid];
    __syncthreads();

    // gather offsets per (tap, sp row); 0xFFFF = OOB/pad
    for (int s = tid; s < 256; s += 128) {
        int g = tile * 256 + s;
        int valid = g < Ntot, m1 = 0, m2 = 0, m3 = 0, m4 = 0;
        if (valid) { m4 = g % n4; int q = g / n4; m3 = q % n3; q /= n3; m2 = q % n2; m1 = q / n2; }
        for (int t = 0; t < T; t++) {
            int off = 0xFFFF;
            if (valid) {
                int a1 = m1 - dd[t][0], a2 = m2 - dd[t][1], a3 = m3 - dd[t][2], a4 = m4 - dd[t][3];
                if (((unsigned)a1 < 12u) & ((unsigned)a2 < 12u) & ((unsigned)a3 < 12u) & ((unsigned)a4 < 12u))
                    off = ((a1 * 12 + a2) * 12 + a3) * 12 + a4;
            }
            offs[t * 256 + s] = (uint16_t)off;
        }
    }
    __syncthreads();   // offs visible to all threads before staging

    const __half* xb = g_x16 + (size_t)b * XM * 64;

    auto stage = [&](int t, int bf) {
        // B: 64 co rows x 128B. 128 threads: 2 threads/row x 4 segs each.
        {
            const int kb = kof[t] * 64;
            int r = tid >> 1, half = tid & 1;
            #pragma unroll
            for (int s = 0; s < 4; s++) {
                int seg = half * 4 + s;
                uint32_t so = bf * 8192 + SWZ(r * 128 + seg * 16);
                cpa16(sb + SM_B + so, g_w16 + (kb + r) * 64 + seg * 8, true);
            }
        }
        // A: 256 sp rows x 128B (8 threads/row, 16 rows/pass)
        {
            const uint16_t* ot = offs + t * 256;
            int q8 = tid & 7, rsub = tid >> 3;
            #pragma unroll
            for (int rb = 0; rb < 256; rb += 16) {
                int r = rb + rsub;
                uint32_t off = ot[r];
                bool ok = off != 0xFFFFu;
                uint32_t so = bf * 32768 + SWZ(r * 128 + q8 * 16);
                cpa16(sb + SM_A + so, xb + (size_t)(ok ? off : 0) * 64 + q8 * 8, ok);
            }
        }
        asm volatile("cp.async.commit_group;" ::: "memory");
    };

    float acc[4][8][4];
    #pragma unroll
    for (int i = 0; i < 4; i++)
        #pragma unroll
        for (int j = 0; j < 8; j++)
            #pragma unroll
            for (int q = 0; q < 4; q++) acc[i][j][q] = 0.f;

    stage(0, 0);

    const int arow_s = lane & 15;
    const int aseg   = ((lane >> 4) & 1) * 16;
    const int brow_s = ((lane >> 4) & 1) * 8 + (lane & 7);
    const int bseg   = ((lane >> 3) & 1) * 16;

    for (int t = 0; t < T; t++) {
        const int bf = t & 1;
        if (t + 1 < T) {
            stage(t + 1, bf ^ 1);
            asm volatile("cp.async.wait_group 1;" ::: "memory");
        } else {
            asm volatile("cp.async.wait_group 0;" ::: "memory");
        }
        __syncthreads();

        const uint32_t abase = sb + SM_A + bf * 32768;
        const uint32_t bbase = sb + SM_B + bf * 8192;

        #pragma unroll
        for (int kk = 0; kk < 4; kk++) {
            uint32_t Af[4][4];
            const uint32_t acol = kk * 32 + aseg;
            #pragma unroll
            for (int i = 0; i < 4; i++)
                ldsm4(Af[i], abase + SWZ((wrp * 64 + i * 16 + arow_s) * 128 + acol));
            #pragma unroll
            for (int jp = 0; jp < 4; jp++) {
                uint32_t Bf[4];
                ldsm4(Bf, bbase + SWZ((jp * 16 + brow_s) * 128 + kk * 32 + bseg));
                #pragma unroll
                for (int i = 0; i < 4; i++) {
                    mma_f16(acc[i][2 * jp],     Af[i], Bf[0], Bf[1]);
                    mma_f16(acc[i][2 * jp + 1], Af[i], Bf[2], Bf[3]);
                }
            }
        }
        if (t + 1 < T) __syncthreads();  // all warps done with bf before restage
    }

    // epilogue: bias, strided scatter into the class sub-grid
    float* ob = out + (size_t)b * OSB;
    const int gbase = tile * 256 + wrp * 64 + (lane >> 2);
    #pragma unroll
    for (int i = 0; i < 4; i++) {
        #pragma unroll
        for (int h = 0; h < 2; h++) {
            int g = gbase + i * 16 + h * 8;
            if (g >= Ntot) continue;
            int m4 = g % n4; int q = g / n4;
            int m3 = q % n3; q /= n3;
            int m2 = q % n2; int m1 = q / n2;
            long o = (long)(2 * m1 + p1) * OS1 + (2 * m2 + p2) * OS2 +
                     (2 * m3 + p3) * OS3 + (2 * m4 + p4);
            float* op = ob + o;
            #pragma unroll
            for (int j = 0; j < 8; j++) {
                int co = j * 8 + (lane & 3) * 2;
                op[(size_t)co * OSC]       = acc[i][j][2 * h]     + bs[co];
                op[(size_t)(co + 1) * OSC] = acc[i][j][2 * h + 1] + bs[co + 1];
            }
        }
    }
}

extern "C" void kernel_launch(void* const* d_in, const int* in_sizes, int n_in,
                              void* d_out, int out_size) {
    const float* x    = (const float*)d_in[0];
    const float* w    = (const float*)d_in[1];
    const float* bias = (const float*)d_in[2];
    float* out = (float*)d_out;

    cudaFuncSetAttribute(ct4d_mma, cudaFuncAttributeMaxDynamicSharedMemorySize, SM_TOTAL);

    wq_prep<<<1296, 256>>>(w);
    xq_prep<<<dim3(648, 4), 256>>>(x);
    // 112 = ceil(13^4 / 256); smaller classes early-exit surplus tiles.
    ct4d_mma<<<dim3(112, 4, 16), 128, SM_TOTAL>>>(bias, out);
}

// round 10
// speedup vs baseline: 3.4469x; 1.0131x over previous
#include <cuda_runtime.h>
#include <cuda_fp16.h>
#include <cstdint>

// ---------------------------------------------------------------------------
// 4D ConvTranspose stride2 K=3^4 as 16 parity-class GEMMs on tensor cores
// (ldmatrix + mma.sync m16n8k16 f16, fp32 accum).
//   D[sp=256, co=64] += X[sp, k]·W[co, k],  k = (tap t, ci),  K = 64*T
// R10: 256 threads / 8 warps (32sp x 64co each) -> 4 warps/SMSP at 2 CTAs/SM
// to hide LDSM/LDGSTS/barrier latency (R9 showed per-tap latency bind, not
// MMA-issue bind). fp16 single-term (rel_err ~2.9e-4, validated).
// ---------------------------------------------------------------------------

#define XM 20736            // 12^4 input spatial points
#define OSB 25000000LL
#define OSC 390625
#define OS1 15625
#define OS2 625
#define OS3 25

// prepped operands
__device__ __align__(16) __half g_w16[81*64*64];   // [kidx][co][ci]
__device__ __align__(16) __half g_x16[4L*XM*64];   // [b][m_lin][ci]

// dynamic SMEM: ping-pong buffers. Rows 128B, XOR-swizzled.
#define SM_A    0            // 2 bufs x 256 rows x 128B = 65536
#define SM_B    65536        // 2 bufs x 64 rows x 128B = 16384
#define SM_OFFS 81920        // u16[16*256] = 8192
#define SM_BIAS 90112        // float[64]
#define SM_KOF  90368        // int[16]
#define SM_DD   90432        // char[16][4]
#define SM_TOTAL 90496

#define SWZ(o) ((o) ^ (((o) >> 3) & 0x70))

// ---------------- prep kernels ----------------
__global__ void wq_prep(const float* __restrict__ w) {
    int idx = blockIdx.x * 256 + threadIdx.x;
    if (idx >= 331776) return;                 // 64*64*81
    int ci = idx / 5184;
    int r  = idx - ci * 5184;
    int co = r / 81;
    int k  = r - co * 81;
    g_w16[(k * 64 + co) * 64 + ci] = __float2half(w[idx]);
}

__global__ void xq_prep(const float* __restrict__ x) {
    __shared__ float s[64][33];
    int b = blockIdx.y, m0 = blockIdx.x * 32, tid = threadIdx.x;
    for (int i = tid; i < 2048; i += 256) {
        int ci = i >> 5, mm = i & 31;
        s[ci][mm] = x[((size_t)(b * 64 + ci)) * XM + m0 + mm];
    }
    __syncthreads();
    int m = tid >> 3, q = tid & 7;
    union { __half a[8]; uint4 v; } hv;
    #pragma unroll
    for (int j = 0; j < 8; j++)
        hv.a[j] = __float2half(s[q * 8 + j][m]);
    *(uint4*)(g_x16 + ((size_t)b * XM + m0 + m) * 64 + q * 8) = hv.v;
}

// ---------------- ptx helpers ----------------
__device__ __forceinline__ uint32_t smem_u32(const void* p) {
    uint32_t a;
    asm("{ .reg .u64 t; cvta.to.shared.u64 t, %1; cvt.u32.u64 %0, t; }" : "=r"(a) : "l"(p));
    return a;
}
__device__ __forceinline__ void ldsm4(uint32_t r[4], uint32_t addr) {
    asm volatile("ldmatrix.sync.aligned.m8n8.x4.shared.b16 {%0,%1,%2,%3}, [%4];"
                 : "=r"(r[0]), "=r"(r[1]), "=r"(r[2]), "=r"(r[3]) : "r"(addr));
}
__device__ __forceinline__ void mma_f16(float c[4], const uint32_t a[4],
                                        uint32_t b0, uint32_t b1) {
    asm volatile("mma.sync.aligned.m16n8k16.row.col.f32.f16.f16.f32 "
                 "{%0,%1,%2,%3}, {%4,%5,%6,%7}, {%8,%9}, {%0,%1,%2,%3};"
                 : "+f"(c[0]), "+f"(c[1]), "+f"(c[2]), "+f"(c[3])
                 : "r"(a[0]), "r"(a[1]), "r"(a[2]), "r"(a[3]), "r"(b0), "r"(b1));
}
__device__ __forceinline__ void cpa16(uint32_t dst, const void* src, bool pred) {
    int sz = pred ? 16 : 0;
    asm volatile("cp.async.cg.shared.global [%0], [%1], 16, %2;"
                 :: "r"(dst), "l"(src), "r"(sz) : "memory");
}

// ---------------- main kernel ----------------
__global__ __launch_bounds__(256) void ct4d_mma(
    const float* __restrict__ bias, float* __restrict__ out)
{
    extern __shared__ char smem[];
    const int tid = threadIdx.x, lane = tid & 31, wrp = tid >> 5;
    const int c = blockIdx.z, b = blockIdx.y, tile = blockIdx.x;
    const int p1 = (c >> 3) & 1, p2 = (c >> 2) & 1, p3 = (c >> 1) & 1, p4 = c & 1;
    const int n1 = 13 - p1, n2 = 13 - p2, n3 = 13 - p3, n4 = 13 - p4;
    const int Ntot = n1 * n2 * n3 * n4;
    if (tile * 256 >= Ntot) return;
    const int lgT = 4 - p1 - p2 - p3 - p4;
    const int T = 1 << lgT;

    const uint32_t sb = smem_u32(smem);
    int*          kof  = (int*)(smem + SM_KOF);
    signed char (*dd)[4] = (signed char(*)[4])(smem + SM_DD);
    uint16_t*     offs = (uint16_t*)(smem + SM_OFFS);
    float*        bs   = (float*)(smem + SM_BIAS);

    if (tid < T) {
        int rem = tid, pp[4] = {p1, p2, p3, p4}, d[4], k[4];
        #pragma unroll
        for (int i = 0; i < 4; i++) {
            if (!pp[i]) { d[i] = rem & 1; rem >>= 1; k[i] = 2 * d[i]; }
            else        { d[i] = 0;                  k[i] = 1; }
        }
        kof[tid] = ((k[0] * 3 + k[1]) * 3 + k[2]) * 3 + k[3];
        dd[tid][0] = d[0]; dd[tid][1] = d[1]; dd[tid][2] = d[2]; dd[tid][3] = d[3];
    }
    if (tid < 64) bs[tid] = bias[tid];
    __syncthreads();

    // gather offsets per (tap, sp row); 0xFFFF = OOB/pad
    {
        int g = tile * 256 + tid;
        int valid = g < Ntot, m1 = 0, m2 = 0, m3 = 0, m4 = 0;
        if (valid) { m4 = g % n4; int q = g / n4; m3 = q % n3; q /= n3; m2 = q % n2; m1 = q / n2; }
        for (int t = 0; t < T; t++) {
            int off = 0xFFFF;
            if (valid) {
                int a1 = m1 - dd[t][0], a2 = m2 - dd[t][1], a3 = m3 - dd[t][2], a4 = m4 - dd[t][3];
                if (((unsigned)a1 < 12u) & ((unsigned)a2 < 12u) & ((unsigned)a3 < 12u) & ((unsigned)a4 < 12u))
                    off = ((a1 * 12 + a2) * 12 + a3) * 12 + a4;
            }
            offs[t * 256 + tid] = (uint16_t)off;
        }
    }
    __syncthreads();   // offs visible to all threads before staging

    const __half* xb = g_x16 + (size_t)b * XM * 64;

    auto stage = [&](int t, int bf) {
        // B: 64 co rows x 128B. 256 threads: 4 threads/row x 2 segs each.
        {
            const int kb = kof[t] * 64;
            int r = tid >> 2, q = tid & 3;
            #pragma unroll
            for (int s = 0; s < 2; s++) {
                int seg = q * 2 + s;
                uint32_t so = bf * 8192 + SWZ(r * 128 + seg * 16);
                cpa16(sb + SM_B + so, g_w16 + (kb + r) * 64 + seg * 8, true);
            }
        }
        // A: 256 sp rows x 128B (8 threads/row, 32 rows/pass, 8 passes)
        {
            const uint16_t* ot = offs + t * 256;
            int q8 = tid & 7, rsub = tid >> 3;
            #pragma unroll
            for (int rb = 0; rb < 256; rb += 32) {
                int r = rb + rsub;
                uint32_t off = ot[r];
                bool ok = off != 0xFFFFu;
                uint32_t so = bf * 32768 + SWZ(r * 128 + q8 * 16);
                cpa16(sb + SM_A + so, xb + (size_t)(ok ? off : 0) * 64 + q8 * 8, ok);
            }
        }
        asm volatile("cp.async.commit_group;" ::: "memory");
    };

    float acc[2][8][4];
    #pragma unroll
    for (int i = 0; i < 2; i++)
        #pragma unroll
        for (int j = 0; j < 8; j++)
            #pragma unroll
            for (int q = 0; q < 4; q++) acc[i][j][q] = 0.f;

    stage(0, 0);

    const int arow_s = lane & 15;
    const int aseg   = ((lane >> 4) & 1) * 16;
    const int brow_s = ((lane >> 4) & 1) * 8 + (lane & 7);
    const int bseg   = ((lane >> 3) & 1) * 16;

    for (int t = 0; t < T; t++) {
        const int bf = t & 1;
        if (t + 1 < T) {
            stage(t + 1, bf ^ 1);
            asm volatile("cp.async.wait_group 1;" ::: "memory");
        } else {
            asm volatile("cp.async.wait_group 0;" ::: "memory");
        }
        __syncthreads();

        const uint32_t abase = sb + SM_A + bf * 32768;
        const uint32_t bbase = sb + SM_B + bf * 8192;

        #pragma unroll
        for (int kk = 0; kk < 4; kk++) {
            uint32_t Af[2][4];
            const uint32_t acol = kk * 32 + aseg;
            #pragma unroll
            for (int i = 0; i < 2; i++)
                ldsm4(Af[i], abase + SWZ((wrp * 32 + i * 16 + arow_s) * 128 + acol));
            #pragma unroll
            for (int jp = 0; jp < 4; jp++) {
                uint32_t Bf[4];
                ldsm4(Bf, bbase + SWZ((jp * 16 + brow_s) * 128 + kk * 32 + bseg));
                #pragma unroll
                for (int i = 0; i < 2; i++) {
                    mma_f16(acc[i][2 * jp],     Af[i], Bf[0], Bf[1]);
                    mma_f16(acc[i][2 * jp + 1], Af[i], Bf[2], Bf[3]);
                }
            }
        }
        if (t + 1 < T) __syncthreads();  // all warps done with bf before restage
    }

    // epilogue: bias, strided scatter into the class sub-grid
    float* ob = out + (size_t)b * OSB;
    const int gbase = tile * 256 + wrp * 32 + (lane >> 2);
    #pragma unroll
    for (int i = 0; i < 2; i++) {
        #pragma unroll
        for (int h = 0; h < 2; h++) {
            int g = gbase + i * 16 + h * 8;
            if (g >= Ntot) continue;
            int m4 = g % n4; int q = g / n4;
            int m3 = q % n3; q /= n3;
            int m2 = q % n2; int m1 = q / n2;
            long o = (long)(2 * m1 + p1) * OS1 + (2 * m2 + p2) * OS2 +
                     (2 * m3 + p3) * OS3 + (2 * m4 + p4);
            float* op = ob + o;
            #pragma unroll
            for (int j = 0; j < 8; j++) {
                int co = j * 8 + (lane & 3) * 2;
                op[(size_t)co * OSC]       = acc[i][j][2 * h]     + bs[co];
                op[(size_t)(co + 1) * OSC] = acc[i][j][2 * h + 1] + bs[co + 1];
            }
        }
    }
}

extern "C" void kernel_launch(void* const* d_in, const int* in_sizes, int n_in,
                              void* d_out, int out_size) {
    const float* x    = (const float*)d_in[0];
    const float* w    = (const float*)d_in[1];
    const float* bias = (const float*)d_in[2];
    float* out = (float*)d_out;

    cudaFuncSetAttribute(ct4d_mma, cudaFuncAttributeMaxDynamicSharedMemorySize, SM_TOTAL);

    wq_prep<<<1296, 256>>>(w);
    xq_prep<<<dim3(648, 4), 256>>>(x);
    // 112 = ceil(13^4 / 256); smaller classes early-exit surplus tiles.
    ct4d_mma<<<dim3(112, 4, 16), 256, SM_TOTAL>>>(bias, out);
}